// round 8
// baseline (speedup 1.0000x reference)
#include <cuda_runtime.h>
#include <cstdint>

#define BB 4
#define HH 8
#define SEQ 2048
#define DM 512
#define DH 64
#define BHN (BB*HH)
#define QT 128
#define KT 128
#define NIT (SEQ/KT)

// ---------------- scratch ---------------------------------------------------
__device__ float g_Q[BHN*SEQ*DH];      // [bh][s][d]
__device__ float g_K[BHN*SEQ*DH];
__device__ float g_V[BHN*SEQ*DH];
__device__ float g_ctx[BB*SEQ*DM];
__device__ float g_tmp[BB*SEQ*DM];
__device__ float g_invl[BHN*SEQ];
__device__ unsigned g_mbits[(size_t)BB*SEQ*(SEQ/32)];   // packed mask bits

// ---------------- helpers ----------------------------------------------------
__device__ __forceinline__ float tf32r(float x) {
    float y; asm("cvt.rna.tf32.f32 %0, %1;" : "=f"(y) : "f"(x)); return y;
}
__device__ __forceinline__ void mma16n8k8(float* d, const uint32_t* a, uint32_t b0, uint32_t b1) {
    asm volatile("mma.sync.aligned.m16n8k8.row.col.f32.tf32.tf32.f32 "
                 "{%0,%1,%2,%3}, {%4,%5,%6,%7}, {%8,%9}, {%0,%1,%2,%3};"
                 : "+f"(d[0]), "+f"(d[1]), "+f"(d[2]), "+f"(d[3])
                 : "r"(a[0]), "r"(a[1]), "r"(a[2]), "r"(a[3]), "r"(b0), "r"(b1));
}
__device__ __forceinline__ void cpa16(void* s, const void* g) {
    uint32_t sa = (uint32_t)__cvta_generic_to_shared(s);
    asm volatile("cp.async.cg.shared.global [%0], [%1], 16;" :: "r"(sa), "l"(g) : "memory");
}
#define CPA_COMMIT() asm volatile("cp.async.commit_group;" ::: "memory")
#define CPA_WAIT(n)  asm volatile("cp.async.wait_group %0;" :: "n"(n) : "memory")

// ---------------- mask bit-pack ---------------------------------------------
__global__ __launch_bounds__(256) void pack_mask_kernel(const int* __restrict__ mask) {
    int gw = (blockIdx.x * 256 + threadIdx.x) >> 5;
    int lane = threadIdx.x & 31;
    size_t base = (size_t)gw * 1024;
    unsigned word = 0;
#pragma unroll
    for (int j = 0; j < 32; j++) {
        int v = mask[base + (size_t)j * 32 + lane];
        unsigned bits = __ballot_sync(0xffffffffu, v != 0);
        if (lane == j) word = bits;
    }
    g_mbits[(size_t)gw * 32 + lane] = word;
}

// ---------------- GEMM via mma.sync tf32, cp.async double buffer -------------
// C[8192x512] = A[8192x512] * W[512x512].  BM=128 BN=128 BK=16, 256 thr, 8 warps.
__global__ __launch_bounds__(256, 2) void gemm_tc_kernel(const float* __restrict__ Ain,
                                                         const float* __restrict__ W,
                                                         int mode) {
    const float* A = (mode == 3) ? g_ctx : Ain;
    __shared__ float As[2][128][20];   // frag bank = (20g+t)&31: perfect perm; row stride 80B (16B-aligned)
    __shared__ float Bs[2][16][136];   // frag bank = (8t+g)&31: perfect perm; row stride 544B

    const int tid = threadIdx.x;
    const int wid = tid >> 5, lane = tid & 31;
    const int g = lane >> 2, t = lane & 3;
    const int wm = (wid & 3) * 32;
    const int wn = (wid >> 2) * 64;
    const int m0 = blockIdx.y * 128, n0 = blockIdx.x * 128;

    const int arow = tid >> 2, ak = (tid & 3) << 2;
    const int brow = tid >> 5, bn = (tid & 31) << 2;
    const float* Ap0 = A + (size_t)(m0 + arow) * DM + ak;
    const float* Ap1 = Ap0 + (size_t)64 * DM;
    const float* Bp0 = W + (size_t)brow * DM + n0 + bn;
    const float* Bp1 = Bp0 + (size_t)8 * DM;

    float Cc[2][8][4];
#pragma unroll
    for (int i = 0; i < 2; i++)
#pragma unroll
        for (int nn = 0; nn < 8; nn++)
#pragma unroll
            for (int r = 0; r < 4; r++) Cc[i][nn][r] = 0.f;

    // prologue: async-stage k-step 0 into buffer 0
    cpa16(&As[0][arow][ak],      Ap0);
    cpa16(&As[0][arow + 64][ak], Ap1);
    cpa16(&Bs[0][brow][bn],      Bp0);
    cpa16(&Bs[0][brow + 8][bn],  Bp1);
    CPA_COMMIT();

    for (int it = 0; it < DM / 16; it++) {
        const int cur = it & 1;
        if (it + 1 < DM / 16) {
            const int nxt = cur ^ 1;
            const int k0n = (it + 1) * 16;
            cpa16(&As[nxt][arow][ak],      Ap0 + k0n);
            cpa16(&As[nxt][arow + 64][ak], Ap1 + k0n);
            cpa16(&Bs[nxt][brow][bn],      Bp0 + (size_t)k0n * DM);
            cpa16(&Bs[nxt][brow + 8][bn],  Bp1 + (size_t)k0n * DM);
            CPA_COMMIT();
            CPA_WAIT(1);
        } else {
            CPA_WAIT(0);
        }
        __syncthreads();

        const uint32_t* AsC = (const uint32_t*)As[cur];
        const uint32_t* BsC = (const uint32_t*)Bs[cur];
#pragma unroll
        for (int kk = 0; kk < 2; kk++) {
            const int kb = kk * 8;
            uint32_t a[2][4];
#pragma unroll
            for (int i = 0; i < 2; i++) {
                int rbase = (wm + i * 16 + g) * 20;
                a[i][0] = AsC[rbase + kb + t];
                a[i][1] = AsC[rbase + 160 + kb + t];
                a[i][2] = AsC[rbase + kb + t + 4];
                a[i][3] = AsC[rbase + 160 + kb + t + 4];
            }
#pragma unroll
            for (int nn = 0; nn < 8; nn++) {
                uint32_t b0 = BsC[(kb + t) * 136 + wn + nn * 8 + g];
                uint32_t b1 = BsC[(kb + t + 4) * 136 + wn + nn * 8 + g];
#pragma unroll
                for (int i = 0; i < 2; i++) mma16n8k8(Cc[i][nn], a[i], b0, b1);
            }
        }
        __syncthreads();
    }

    // epilogue: rows (wm+16i+g, +8), cols (wn+nn*8+2t, +1); h=(n0+coln)>>6
    const int hbase = n0 >> 6;
#pragma unroll
    for (int i = 0; i < 2; i++) {
#pragma unroll
        for (int rr = 0; rr < 2; rr++) {
            int m = m0 + wm + i * 16 + g + rr * 8;
            int bidx = m >> 11, s = m & 2047;
#pragma unroll
            for (int nn = 0; nn < 8; nn++) {
                int coln = wn + nn * 8 + 2 * t;
                float2 v = make_float2(Cc[i][nn][rr * 2 + 0], Cc[i][nn][rr * 2 + 1]);
                if (mode == 3) {
                    *(float2*)&g_tmp[(size_t)m * DM + n0 + coln] = v;
                } else {
                    int h = hbase + (coln >> 6);
                    int d = coln & 63;
                    float* dst = (mode == 0) ? g_Q : (mode == 1) ? g_K : g_V;
                    *(float2*)&dst[(((size_t)bidx * HH + h) * SEQ + s) * DH + d] = v;
                }
            }
        }
    }
}

// ---------------- tensor-core attention via mma.sync tf32 --------------------
// 256 threads (8 warps); block = 128 q rows of one (b,h); warp w owns rows w*16..+15.
// K/V staged via cp.async (raw fp32 -> HW tf32 truncation); Q staged once w/ RNA.
__global__ __launch_bounds__(256, 2) void attn_mma_kernel(float* __restrict__ attn_out) {
    extern __shared__ float sm[];
    float* Ks = sm;                    // [128][68]
    float* Vs = sm + 128 * 68;         // [128][68]
    uint32_t* KsU = (uint32_t*)Ks;
    uint32_t* VsU = (uint32_t*)Vs;

    const int tid  = threadIdx.x;
    const int w    = tid >> 5;
    const int lane = tid & 31;
    const int gid  = lane >> 2;
    const int cL   = lane & 3;
    const int bh   = blockIdx.y;
    const int b    = bh >> 3, h = bh & 7;
    const int q0   = blockIdx.x * QT;
    const int lr   = w * 16 + gid;     // 0..119 (this thread: lr and lr+8)

    const float* Qg = g_Q + (size_t)bh * SEQ * DH;
    const float* Kg = g_K + (size_t)bh * SEQ * DH;
    const float* Vg = g_V + (size_t)bh * SEQ * DH;

    // stage Q tile [128][64] (RNA tf32) through Ks region
#pragma unroll
    for (int j = 0; j < 8; j++) {
        int flat = j * 256 + tid;
        int row = flat >> 4, d4 = flat & 15;
        float4 v = *(const float4*)(Qg + (size_t)(q0 + row) * DH + d4 * 4);
        v.x = tf32r(v.x); v.y = tf32r(v.y); v.z = tf32r(v.z); v.w = tf32r(v.w);
        *(float4*)&Ks[row * 68 + d4 * 4] = v;
    }
    __syncthreads();

    uint32_t qa[8][4];
#pragma unroll
    for (int kk = 0; kk < 8; kk++) {
        qa[kk][0] = KsU[lr * 68 + kk * 8 + cL];
        qa[kk][1] = KsU[(lr + 8) * 68 + kk * 8 + cL];
        qa[kk][2] = KsU[lr * 68 + kk * 8 + cL + 4];
        qa[kk][3] = KsU[(lr + 8) * 68 + kk * 8 + cL + 4];
    }

    float Cacc[8][4];
#pragma unroll
    for (int dt = 0; dt < 8; dt++)
#pragma unroll
        for (int r = 0; r < 4; r++) Cacc[dt][r] = 0.f;
    float lsum0 = 0.f, lsum1 = 0.f;

    const size_t mrow0 = ((size_t)b * SEQ + q0 + lr) * (SEQ / 32);
    const size_t mrow1 = ((size_t)b * SEQ + q0 + lr + 8) * (SEQ / 32);
    float* aprow0 = attn_out + ((size_t)bh * SEQ + q0 + lr) * SEQ;
    float* aprow1 = aprow0 + 8 * SEQ;

    for (int i = 0; i < NIT; i++) {
        const int k0 = i * KT;
        __syncthreads();   // prior iteration (or Q-frag preload) done reading Ks/Vs

        // stage K and V tiles via cp.async (raw)
#pragma unroll
        for (int j = 0; j < 8; j++) {
            int flat = j * 256 + tid;
            int row = flat >> 4, d4 = flat & 15;
            cpa16(&Ks[row * 68 + d4 * 4], Kg + (size_t)(k0 + row) * DH + d4 * 4);
            cpa16(&Vs[row * 68 + d4 * 4], Vg + (size_t)(k0 + row) * DH + d4 * 4);
        }
        CPA_COMMIT();
        CPA_WAIT(0);
        __syncthreads();

        // QK
        float S[16][4];
#pragma unroll
        for (int n = 0; n < 16; n++)
#pragma unroll
            for (int r = 0; r < 4; r++) S[n][r] = 0.f;
#pragma unroll
        for (int kk = 0; kk < 8; kk++) {
#pragma unroll
            for (int n = 0; n < 16; n++) {
                uint32_t b0 = KsU[(n * 8 + gid) * 68 + kk * 8 + cL];
                uint32_t b1 = KsU[(n * 8 + gid) * 68 + kk * 8 + cL + 4];
                mma16n8k8(S[n], qa[kk], b0, b1);
            }
        }

        // mask + exp (MUFU) + attn STG + row-sum
        uint4 m4l = *(const uint4*)&g_mbits[mrow0 + (k0 >> 5)];
        uint4 m4h = *(const uint4*)&g_mbits[mrow1 + (k0 >> 5)];
        unsigned ml[4] = {m4l.x, m4l.y, m4l.z, m4l.w};
        unsigned mh[4] = {m4h.x, m4h.y, m4h.z, m4h.w};
#pragma unroll
        for (int n = 0; n < 16; n++) {
            int shift = (n & 3) * 8 + 2 * cL;
            unsigned bl = ml[n >> 2] >> shift;
            unsigned bhh = mh[n >> 2] >> shift;
            float e0 = (bl  & 1u) ? 0.f : __expf(S[n][0] * 0.125f);
            float e1 = (bl  & 2u) ? 0.f : __expf(S[n][1] * 0.125f);
            float e2 = (bhh & 1u) ? 0.f : __expf(S[n][2] * 0.125f);
            float e3 = (bhh & 2u) ? 0.f : __expf(S[n][3] * 0.125f);
            lsum0 += e0 + e1;
            lsum1 += e2 + e3;
            int col = k0 + n * 8 + 2 * cL;
            *(float2*)(aprow0 + col) = make_float2(e0, e1);
            *(float2*)(aprow1 + col) = make_float2(e2, e3);
            S[n][0] = e0; S[n][1] = e1; S[n][2] = e2; S[n][3] = e3;
        }

        // PV (P raw bits -> HW tf32 truncation)
        const int src  = (lane & ~3) | (cL >> 1);
        const int src2 = src + 2;
#pragma unroll
        for (int kk = 0; kk < 16; kk++) {
            float t00 = __shfl_sync(0xffffffffu, S[kk][0], src);
            float t01 = __shfl_sync(0xffffffffu, S[kk][1], src);
            float t20 = __shfl_sync(0xffffffffu, S[kk][0], src2);
            float t21 = __shfl_sync(0xffffffffu, S[kk][1], src2);
            float u00 = __shfl_sync(0xffffffffu, S[kk][2], src);
            float u01 = __shfl_sync(0xffffffffu, S[kk][3], src);
            float u20 = __shfl_sync(0xffffffffu, S[kk][2], src2);
            float u21 = __shfl_sync(0xffffffffu, S[kk][3], src2);
            uint32_t pa[4];
            pa[0] = __float_as_uint((cL & 1) ? t01 : t00);
            pa[1] = __float_as_uint((cL & 1) ? u01 : u00);
            pa[2] = __float_as_uint((cL & 1) ? t21 : t20);
            pa[3] = __float_as_uint((cL & 1) ? u21 : u20);
#pragma unroll
            for (int dt = 0; dt < 8; dt++) {
                uint32_t b0 = VsU[(kk * 8 + cL) * 68 + dt * 8 + gid];
                uint32_t b1 = VsU[(kk * 8 + cL + 4) * 68 + dt * 8 + gid];
                mma16n8k8(Cacc[dt], pa, b0, b1);
            }
        }
    }

    lsum0 += __shfl_xor_sync(0xffffffffu, lsum0, 1);
    lsum0 += __shfl_xor_sync(0xffffffffu, lsum0, 2);
    lsum1 += __shfl_xor_sync(0xffffffffu, lsum1, 1);
    lsum1 += __shfl_xor_sync(0xffffffffu, lsum1, 2);
    float inv0 = 1.0f / lsum0;
    float inv1 = 1.0f / lsum1;
    if (cL == 0) {
        g_invl[(size_t)bh * SEQ + q0 + lr]     = inv0;
        g_invl[(size_t)bh * SEQ + q0 + lr + 8] = inv1;
    }
    float* cp0 = g_ctx + ((size_t)b * SEQ + q0 + lr) * DM + h * DH;
    float* cp1 = cp0 + 8 * DM;
#pragma unroll
    for (int dt = 0; dt < 8; dt++) {
        int col = dt * 8 + 2 * cL;
        *(float2*)(cp0 + col) = make_float2(Cacc[dt][0] * inv0, Cacc[dt][1] * inv0);
        *(float2*)(cp1 + col) = make_float2(Cacc[dt][2] * inv1, Cacc[dt][3] * inv1);
    }
}

// ---------------- scale attn rows by 1/l ------------------------------------
__global__ void attn_norm_kernel(float* __restrict__ attn) {
    size_t i4 = (size_t)blockIdx.x * 256 + threadIdx.x;
    float inv = g_invl[i4 >> 9];
    float4* p = (float4*)attn + i4;
    float4 v = *p;
    v.x *= inv; v.y *= inv; v.z *= inv; v.w *= inv;
    *p = v;
}

// ---------------- layernorm(tmp + input_Q) ----------------------------------
__global__ __launch_bounds__(256) void ln_kernel(const float* __restrict__ inQ,
                                                 const float* __restrict__ gamma,
                                                 const float* __restrict__ beta,
                                                 float* __restrict__ out) {
    int row = blockIdx.x;
    int tid = threadIdx.x;
    const float* t  = g_tmp + (size_t)row * DM;
    const float* xq = inQ  + (size_t)row * DM;
    float2 a  = *(const float2*)(t  + tid * 2);
    float2 b2 = *(const float2*)(xq + tid * 2);
    float x0 = a.x + b2.x, x1 = a.y + b2.y;
    float s  = x0 + x1;
    float sq = x0 * x0 + x1 * x1;
#pragma unroll
    for (int o = 16; o; o >>= 1) {
        s  += __shfl_xor_sync(0xffffffffu, s,  o);
        sq += __shfl_xor_sync(0xffffffffu, sq, o);
    }
    __shared__ float ws[8], wq[8];
    int w = tid >> 5, lane = tid & 31;
    if (lane == 0) { ws[w] = s; wq[w] = sq; }
    __syncthreads();
    float ts = 0.f, tq = 0.f;
#pragma unroll
    for (int k = 0; k < 8; k++) { ts += ws[k]; tq += wq[k]; }
    float mu  = ts * (1.f / DM);
    float var = tq * (1.f / DM) - mu * mu;
    float r = rsqrtf(var + 1e-5f);
    float2 g  = *(const float2*)(gamma + tid * 2);
    float2 be = *(const float2*)(beta  + tid * 2);
    float2 o;
    o.x = (x0 - mu) * r * g.x + be.x;
    o.y = (x1 - mu) * r * g.y + be.y;
    *(float2*)(out + (size_t)row * DM + tid * 2) = o;
}

// ---------------- launch ----------------------------------------------------
extern "C" void kernel_launch(void* const* d_in, const int* in_sizes, int n_in,
                              void* d_out, int out_size) {
    const float* inQ  = (const float*)d_in[0];
    const float* inK  = (const float*)d_in[1];
    const float* inV  = (const float*)d_in[2];
    const int*   mask = (const int*)d_in[3];
    const float* WQ   = (const float*)d_in[4];
    const float* WK   = (const float*)d_in[5];
    const float* WV   = (const float*)d_in[6];
    const float* Wfc  = (const float*)d_in[7];
    const float* gamma = (const float*)d_in[8];
    const float* beta  = (const float*)d_in[9];

    float* out = (float*)d_out;
    const long OUT_ELEMS = (long)BB * SEQ * DM;
    float* attn_out = out + OUT_ELEMS;

    pack_mask_kernel<<<2048, 256>>>(mask);

    dim3 gb(4, 64);
    gemm_tc_kernel<<<gb, 256>>>(inQ, WQ, 0);
    gemm_tc_kernel<<<gb, 256>>>(inK, WK, 1);
    gemm_tc_kernel<<<gb, 256>>>(inV, WV, 2);

    const int SMEM_ATTN = 2 * 128 * 68 * 4;   // 69632 B
    cudaFuncSetAttribute(attn_mma_kernel, cudaFuncAttributeMaxDynamicSharedMemorySize, SMEM_ATTN);
    attn_mma_kernel<<<dim3(SEQ / QT, BHN), 256, SMEM_ATTN>>>(attn_out);

    attn_norm_kernel<<<131072, 256>>>(attn_out);

    gemm_tc_kernel<<<gb, 256>>>(inQ /*ignored*/, Wfc, 3);
    ln_kernel<<<BB * SEQ, 256>>>(inQ, gamma, beta, out);
}

// round 10
// speedup vs baseline: 1.0152x; 1.0152x over previous
#include <cuda_runtime.h>
#include <cstdint>

#define BB 4
#define HH 8
#define SEQ 2048
#define DM 512
#define DH 64
#define BHN (BB*HH)
#define QT 128
#define KT 64
#define NIT (SEQ/KT)

// ---------------- scratch ---------------------------------------------------
__device__ float g_Q[BHN*SEQ*DH];      // [bh][s][d]
__device__ float g_K[BHN*SEQ*DH];
__device__ float g_V[BHN*SEQ*DH];
__device__ float g_ctx[BB*SEQ*DM];
__device__ float g_tmp[BB*SEQ*DM];
__device__ float g_invl[BHN*SEQ];
__device__ unsigned g_mbits[(size_t)BB*SEQ*(SEQ/32)];   // packed mask bits

// ---------------- helpers ----------------------------------------------------
__device__ __forceinline__ float tf32r(float x) {
    float y; asm("cvt.rna.tf32.f32 %0, %1;" : "=f"(y) : "f"(x)); return y;
}
__device__ __forceinline__ void mma16n8k8(float* d, const uint32_t* a, uint32_t b0, uint32_t b1) {
    asm volatile("mma.sync.aligned.m16n8k8.row.col.f32.tf32.tf32.f32 "
                 "{%0,%1,%2,%3}, {%4,%5,%6,%7}, {%8,%9}, {%0,%1,%2,%3};"
                 : "+f"(d[0]), "+f"(d[1]), "+f"(d[2]), "+f"(d[3])
                 : "r"(a[0]), "r"(a[1]), "r"(a[2]), "r"(a[3]), "r"(b0), "r"(b1));
}
__device__ __forceinline__ void cpa16(void* s, const void* g) {
    uint32_t sa = (uint32_t)__cvta_generic_to_shared(s);
    asm volatile("cp.async.cg.shared.global [%0], [%1], 16;" :: "r"(sa), "l"(g) : "memory");
}
#define CPA_COMMIT() asm volatile("cp.async.commit_group;" ::: "memory")
#define CPA_WAIT(n)  asm volatile("cp.async.wait_group %0;" :: "n"(n) : "memory")

// ---------------- mask bit-pack ---------------------------------------------
__global__ __launch_bounds__(256) void pack_mask_kernel(const int* __restrict__ mask) {
    int gw = (blockIdx.x * 256 + threadIdx.x) >> 5;
    int lane = threadIdx.x & 31;
    size_t base = (size_t)gw * 1024;
    unsigned word = 0;
#pragma unroll
    for (int j = 0; j < 32; j++) {
        int v = mask[base + (size_t)j * 32 + lane];
        unsigned bits = __ballot_sync(0xffffffffu, v != 0);
        if (lane == j) word = bits;
    }
    g_mbits[(size_t)gw * 32 + lane] = word;
}

// ---------------- GEMM via mma.sync tf32, cp.async double buffer -------------
__global__ __launch_bounds__(256, 2) void gemm_tc_kernel(const float* __restrict__ Ain,
                                                         const float* __restrict__ W,
                                                         int mode) {
    const float* A = (mode == 3) ? g_ctx : Ain;
    __shared__ float As[2][128][20];
    __shared__ float Bs[2][16][136];

    const int tid = threadIdx.x;
    const int wid = tid >> 5, lane = tid & 31;
    const int g = lane >> 2, t = lane & 3;
    const int wm = (wid & 3) * 32;
    const int wn = (wid >> 2) * 64;
    const int m0 = blockIdx.y * 128, n0 = blockIdx.x * 128;

    const int arow = tid >> 2, ak = (tid & 3) << 2;
    const int brow = tid >> 5, bn = (tid & 31) << 2;
    const float* Ap0 = A + (size_t)(m0 + arow) * DM + ak;
    const float* Ap1 = Ap0 + (size_t)64 * DM;
    const float* Bp0 = W + (size_t)brow * DM + n0 + bn;
    const float* Bp1 = Bp0 + (size_t)8 * DM;

    float Cc[2][8][4];
#pragma unroll
    for (int i = 0; i < 2; i++)
#pragma unroll
        for (int nn = 0; nn < 8; nn++)
#pragma unroll
            for (int r = 0; r < 4; r++) Cc[i][nn][r] = 0.f;

    cpa16(&As[0][arow][ak],      Ap0);
    cpa16(&As[0][arow + 64][ak], Ap1);
    cpa16(&Bs[0][brow][bn],      Bp0);
    cpa16(&Bs[0][brow + 8][bn],  Bp1);
    CPA_COMMIT();

    for (int it = 0; it < DM / 16; it++) {
        const int cur = it & 1;
        if (it + 1 < DM / 16) {
            const int nxt = cur ^ 1;
            const int k0n = (it + 1) * 16;
            cpa16(&As[nxt][arow][ak],      Ap0 + k0n);
            cpa16(&As[nxt][arow + 64][ak], Ap1 + k0n);
            cpa16(&Bs[nxt][brow][bn],      Bp0 + (size_t)k0n * DM);
            cpa16(&Bs[nxt][brow + 8][bn],  Bp1 + (size_t)k0n * DM);
            CPA_COMMIT();
            CPA_WAIT(1);
        } else {
            CPA_WAIT(0);
        }
        __syncthreads();

        const uint32_t* AsC = (const uint32_t*)As[cur];
        const uint32_t* BsC = (const uint32_t*)Bs[cur];
#pragma unroll
        for (int kk = 0; kk < 2; kk++) {
            const int kb = kk * 8;
            uint32_t a[2][4];
#pragma unroll
            for (int i = 0; i < 2; i++) {
                int rbase = (wm + i * 16 + g) * 20;
                a[i][0] = AsC[rbase + kb + t];
                a[i][1] = AsC[rbase + 160 + kb + t];
                a[i][2] = AsC[rbase + kb + t + 4];
                a[i][3] = AsC[rbase + 160 + kb + t + 4];
            }
#pragma unroll
            for (int nn = 0; nn < 8; nn++) {
                uint32_t b0 = BsC[(kb + t) * 136 + wn + nn * 8 + g];
                uint32_t b1 = BsC[(kb + t + 4) * 136 + wn + nn * 8 + g];
#pragma unroll
                for (int i = 0; i < 2; i++) mma16n8k8(Cc[i][nn], a[i], b0, b1);
            }
        }
        __syncthreads();
    }

    const int hbase = n0 >> 6;
#pragma unroll
    for (int i = 0; i < 2; i++) {
#pragma unroll
        for (int rr = 0; rr < 2; rr++) {
            int m = m0 + wm + i * 16 + g + rr * 8;
            int bidx = m >> 11, s = m & 2047;
#pragma unroll
            for (int nn = 0; nn < 8; nn++) {
                int coln = wn + nn * 8 + 2 * t;
                float2 v = make_float2(Cc[i][nn][rr * 2 + 0], Cc[i][nn][rr * 2 + 1]);
                if (mode == 3) {
                    *(float2*)&g_tmp[(size_t)m * DM + n0 + coln] = v;
                } else {
                    int h = hbase + (coln >> 6);
                    int d = coln & 63;
                    float* dst = (mode == 0) ? g_Q : (mode == 1) ? g_K : g_V;
                    *(float2*)&dst[(((size_t)bidx * HH + h) * SEQ + s) * DH + d] = v;
                }
            }
        }
    }
}

// ---------------- tensor-core attention: cp.async double-buffered K/V --------
// 256 threads (8 warps); block = 128 q rows of one (b,h); warp w owns rows w*16..+15.
// KT=64 k-tiles ping-ponged: stage tile i+1 during compute of tile i.
// SMEM: buf[2] x { K[64][68], V[64][68] } = 69632 B; Q staged through buf0 once.
#define TILE_F (64 * 68)                 // floats per K or V tile
#define BUF_F  (2 * TILE_F)              // floats per buffer (K+V)
__global__ __launch_bounds__(256, 2) void attn_mma_kernel(float* __restrict__ attn_out) {
    extern __shared__ float sm[];

    const int tid  = threadIdx.x;
    const int w    = tid >> 5;
    const int lane = tid & 31;
    const int gid  = lane >> 2;
    const int cL   = lane & 3;
    const int bh   = blockIdx.y;
    const int b    = bh >> 3, h = bh & 7;
    const int q0   = blockIdx.x * QT;
    const int lr   = w * 16 + gid;       // this thread: rows lr and lr+8

    const float* Qg = g_Q + (size_t)bh * SEQ * DH;
    const float* Kg = g_K + (size_t)bh * SEQ * DH;
    const float* Vg = g_V + (size_t)bh * SEQ * DH;

    // ---- stage Q tile [128][64] (RNA tf32) through buf area, grab frags ----
#pragma unroll
    for (int j = 0; j < 8; j++) {
        int flat = j * 256 + tid;
        int row = flat >> 4, d4 = flat & 15;
        float4 v = *(const float4*)(Qg + (size_t)(q0 + row) * DH + d4 * 4);
        v.x = tf32r(v.x); v.y = tf32r(v.y); v.z = tf32r(v.z); v.w = tf32r(v.w);
        *(float4*)&sm[row * 68 + d4 * 4] = v;
    }
    __syncthreads();
    uint32_t qa[8][4];
    {
        const uint32_t* QsU = (const uint32_t*)sm;
#pragma unroll
        for (int kk = 0; kk < 8; kk++) {
            qa[kk][0] = QsU[lr * 68 + kk * 8 + cL];
            qa[kk][1] = QsU[(lr + 8) * 68 + kk * 8 + cL];
            qa[kk][2] = QsU[lr * 68 + kk * 8 + cL + 4];
            qa[kk][3] = QsU[(lr + 8) * 68 + kk * 8 + cL + 4];
        }
    }
    __syncthreads();   // all Q reads done before cp.async overwrites the region

    float Cacc[8][4];
#pragma unroll
    for (int dt = 0; dt < 8; dt++)
#pragma unroll
        for (int r = 0; r < 4; r++) Cacc[dt][r] = 0.f;
    float lsum0 = 0.f, lsum1 = 0.f;

    const size_t mrow0 = ((size_t)b * SEQ + q0 + lr) * (SEQ / 32);
    const size_t mrow1 = ((size_t)b * SEQ + q0 + lr + 8) * (SEQ / 32);
    float* aprow0 = attn_out + ((size_t)bh * SEQ + q0 + lr) * SEQ;
    float* aprow1 = aprow0 + 8 * SEQ;

    // per-thread staging: 4 threads/row, thread covers floats [16*(tid&3), +16)
    const int srow = tid >> 2;           // 0..63
    const int sd4  = (tid & 3) << 4;     // 0,16,32,48  (FIX: was <<2 -> partial coverage)

    // prologue: stage tile 0 into buf0
    {
        const float* kp = Kg + (size_t)srow * DH + sd4;
        const float* vp = Vg + (size_t)srow * DH + sd4;
        float* kb = sm + srow * 68 + sd4;
        float* vb = sm + TILE_F + srow * 68 + sd4;
#pragma unroll
        for (int u = 0; u < 4; u++) {
            cpa16(kb + u * 4, kp + u * 4);
            cpa16(vb + u * 4, vp + u * 4);
        }
    }
    CPA_COMMIT();

    for (int i = 0; i < NIT; i++) {
        const int k0 = i * KT;
        const int cur = i & 1;
        if (i + 1 < NIT) {
            const int nxt = cur ^ 1;
            const size_t off = (size_t)(i + 1) * KT * DH + (size_t)srow * DH + sd4;
            float* kb = sm + nxt * BUF_F + srow * 68 + sd4;
            float* vb = sm + nxt * BUF_F + TILE_F + srow * 68 + sd4;
#pragma unroll
            for (int u = 0; u < 4; u++) {
                cpa16(kb + u * 4, Kg + off + u * 4);
                cpa16(vb + u * 4, Vg + off + u * 4);
            }
            CPA_COMMIT();
            CPA_WAIT(1);
        } else {
            CPA_WAIT(0);
        }
        __syncthreads();

        const uint32_t* KsU = (const uint32_t*)(sm + cur * BUF_F);
        const uint32_t* VsU = KsU + TILE_F;

        // QK: S[16 q][64 k] per warp
        float S[8][4];
#pragma unroll
        for (int n = 0; n < 8; n++)
#pragma unroll
            for (int r = 0; r < 4; r++) S[n][r] = 0.f;
#pragma unroll
        for (int kk = 0; kk < 8; kk++) {
#pragma unroll
            for (int n = 0; n < 8; n++) {
                uint32_t b0 = KsU[(n * 8 + gid) * 68 + kk * 8 + cL];
                uint32_t b1 = KsU[(n * 8 + gid) * 68 + kk * 8 + cL + 4];
                mma16n8k8(S[n], qa[kk], b0, b1);
            }
        }

        // mask + exp + attn STG + row-sum
        uint2 m2l = *(const uint2*)&g_mbits[mrow0 + (k0 >> 5)];
        uint2 m2h = *(const uint2*)&g_mbits[mrow1 + (k0 >> 5)];
        unsigned ml[2] = {m2l.x, m2l.y};
        unsigned mh[2] = {m2h.x, m2h.y};
#pragma unroll
        for (int n = 0; n < 8; n++) {
            int shift = (n & 3) * 8 + 2 * cL;
            unsigned bl  = ml[n >> 2] >> shift;
            unsigned bhh = mh[n >> 2] >> shift;
            float e0 = (bl  & 1u) ? 0.f : __expf(S[n][0] * 0.125f);
            float e1 = (bl  & 2u) ? 0.f : __expf(S[n][1] * 0.125f);
            float e2 = (bhh & 1u) ? 0.f : __expf(S[n][2] * 0.125f);
            float e3 = (bhh & 2u) ? 0.f : __expf(S[n][3] * 0.125f);
            lsum0 += e0 + e1;
            lsum1 += e2 + e3;
            int col = k0 + n * 8 + 2 * cL;
            *(float2*)(aprow0 + col) = make_float2(e0, e1);
            *(float2*)(aprow1 + col) = make_float2(e2, e3);
            S[n][0] = e0; S[n][1] = e1; S[n][2] = e2; S[n][3] = e3;
        }

        // PV: ctx += P.V
        const int src  = (lane & ~3) | (cL >> 1);
        const int src2 = src + 2;
#pragma unroll
        for (int kk = 0; kk < 8; kk++) {
            float t00 = __shfl_sync(0xffffffffu, S[kk][0], src);
            float t01 = __shfl_sync(0xffffffffu, S[kk][1], src);
            float t20 = __shfl_sync(0xffffffffu, S[kk][0], src2);
            float t21 = __shfl_sync(0xffffffffu, S[kk][1], src2);
            float u00 = __shfl_sync(0xffffffffu, S[kk][2], src);
            float u01 = __shfl_sync(0xffffffffu, S[kk][3], src);
            float u20 = __shfl_sync(0xffffffffu, S[kk][2], src2);
            float u21 = __shfl_sync(0xffffffffu, S[kk][3], src2);
            uint32_t pa[4];
            pa[0] = __float_as_uint((cL & 1) ? t01 : t00);
            pa[1] = __float_as_uint((cL & 1) ? u01 : u00);
            pa[2] = __float_as_uint((cL & 1) ? t21 : t20);
            pa[3] = __float_as_uint((cL & 1) ? u21 : u20);
#pragma unroll
            for (int dt = 0; dt < 8; dt++) {
                uint32_t b0 = VsU[(kk * 8 + cL) * 68 + dt * 8 + gid];
                uint32_t b1 = VsU[(kk * 8 + cL + 4) * 68 + dt * 8 + gid];
                mma16n8k8(Cacc[dt], pa, b0, b1);
            }
        }
        __syncthreads();
    }

    lsum0 += __shfl_xor_sync(0xffffffffu, lsum0, 1);
    lsum0 += __shfl_xor_sync(0xffffffffu, lsum0, 2);
    lsum1 += __shfl_xor_sync(0xffffffffu, lsum1, 1);
    lsum1 += __shfl_xor_sync(0xffffffffu, lsum1, 2);
    float inv0 = 1.0f / lsum0;
    float inv1 = 1.0f / lsum1;
    if (cL == 0) {
        g_invl[(size_t)bh * SEQ + q0 + lr]     = inv0;
        g_invl[(size_t)bh * SEQ + q0 + lr + 8] = inv1;
    }
    float* cp0 = g_ctx + ((size_t)b * SEQ + q0 + lr) * DM + h * DH;
    float* cp1 = cp0 + 8 * DM;
#pragma unroll
    for (int dt = 0; dt < 8; dt++) {
        int col = dt * 8 + 2 * cL;
        *(float2*)(cp0 + col) = make_float2(Cacc[dt][0] * inv0, Cacc[dt][1] * inv0);
        *(float2*)(cp1 + col) = make_float2(Cacc[dt][2] * inv1, Cacc[dt][3] * inv1);
    }
}

// ---------------- scale attn rows by 1/l ------------------------------------
__global__ void attn_norm_kernel(float* __restrict__ attn) {
    size_t i4 = (size_t)blockIdx.x * 256 + threadIdx.x;
    float inv = g_invl[i4 >> 9];
    float4* p = (float4*)attn + i4;
    float4 v = *p;
    v.x *= inv; v.y *= inv; v.z *= inv; v.w *= inv;
    *p = v;
}

// ---------------- layernorm(tmp + input_Q) ----------------------------------
__global__ __launch_bounds__(256) void ln_kernel(const float* __restrict__ inQ,
                                                 const float* __restrict__ gamma,
                                                 const float* __restrict__ beta,
                                                 float* __restrict__ out) {
    int row = blockIdx.x;
    int tid = threadIdx.x;
    const float* t  = g_tmp + (size_t)row * DM;
    const float* xq = inQ  + (size_t)row * DM;
    float2 a  = *(const float2*)(t  + tid * 2);
    float2 b2 = *(const float2*)(xq + tid * 2);
    float x0 = a.x + b2.x, x1 = a.y + b2.y;
    float s  = x0 + x1;
    float sq = x0 * x0 + x1 * x1;
#pragma unroll
    for (int o = 16; o; o >>= 1) {
        s  += __shfl_xor_sync(0xffffffffu, s,  o);
        sq += __shfl_xor_sync(0xffffffffu, sq, o);
    }
    __shared__ float ws[8], wq[8];
    int w = tid >> 5, lane = tid & 31;
    if (lane == 0) { ws[w] = s; wq[w] = sq; }
    __syncthreads();
    float ts = 0.f, tq = 0.f;
#pragma unroll
    for (int k = 0; k < 8; k++) { ts += ws[k]; tq += wq[k]; }
    float mu  = ts * (1.f / DM);
    float var = tq * (1.f / DM) - mu * mu;
    float r = rsqrtf(var + 1e-5f);
    float2 g  = *(const float2*)(gamma + tid * 2);
    float2 be = *(const float2*)(beta  + tid * 2);
    float2 o;
    o.x = (x0 - mu) * r * g.x + be.x;
    o.y = (x1 - mu) * r * g.y + be.y;
    *(float2*)(out + (size_t)row * DM + tid * 2) = o;
}

// ---------------- launch ----------------------------------------------------
extern "C" void kernel_launch(void* const* d_in, const int* in_sizes, int n_in,
                              void* d_out, int out_size) {
    const float* inQ  = (const float*)d_in[0];
    const float* inK  = (const float*)d_in[1];
    const float* inV  = (const float*)d_in[2];
    const int*   mask = (const int*)d_in[3];
    const float* WQ   = (const float*)d_in[4];
    const float* WK   = (const float*)d_in[5];
    const float* WV   = (const float*)d_in[6];
    const float* Wfc  = (const float*)d_in[7];
    const float* gamma = (const float*)d_in[8];
    const float* beta  = (const float*)d_in[9];

    float* out = (float*)d_out;
    const long OUT_ELEMS = (long)BB * SEQ * DM;
    float* attn_out = out + OUT_ELEMS;

    pack_mask_kernel<<<2048, 256>>>(mask);

    dim3 gb(4, 64);
    gemm_tc_kernel<<<gb, 256>>>(inQ, WQ, 0);
    gemm_tc_kernel<<<gb, 256>>>(inK, WK, 1);
    gemm_tc_kernel<<<gb, 256>>>(inV, WV, 2);

    const int SMEM_ATTN = 2 * BUF_F * 4;   // 69632 B
    cudaFuncSetAttribute(attn_mma_kernel, cudaFuncAttributeMaxDynamicSharedMemorySize, SMEM_ATTN);
    attn_mma_kernel<<<dim3(SEQ / QT, BHN), 256, SMEM_ATTN>>>(attn_out);

    attn_norm_kernel<<<131072, 256>>>(attn_out);

    gemm_tc_kernel<<<gb, 256>>>(inQ /*ignored*/, Wfc, 3);
    ln_kernel<<<BB * SEQ, 256>>>(inQ, gamma, beta, out);
}